// round 1
// baseline (speedup 1.0000x reference)
#include <cuda_runtime.h>
#include <cuda_bf16.h>

// Problem constants (DcrROIHead_80745385165042)
#define BATCH 16
#define MGT 256          // gt boxes per image
#define NPROP 8192       // proposals per image
#define NUM_CLASSES 80
#define KFG 128
#define KBG 384
#define NSAMP 512
#define SORT_THREADS 1024

// Scratch: sort keys for [fg|bg] x batch x proposals (2 MB, device global — no allocs)
__device__ unsigned long long g_keys[2ULL * BATCH * NPROP];

// ---------------------------------------------------------------------------
// Kernel A: per-proposal max-IoU match over 256 GT boxes (division-free inner
// loop via cross-multiplication), writes matched_vals + matched_idxs into
// d_out and builds the fg/bg sort keys.
// ---------------------------------------------------------------------------
__global__ __launch_bounds__(256)
void iou_match_kernel(const float4* __restrict__ gt_boxes,
                      const float4* __restrict__ prop_boxes,
                      const float* __restrict__ rand_priority,
                      float* __restrict__ out)
{
    __shared__ float4 sg[MGT];
    __shared__ float sarea[MGT];

    const int b   = blockIdx.y;
    const int tid = threadIdx.x;

    // blockDim.x == 256 == MGT: one gt box per thread
    {
        float4 g = gt_boxes[b * MGT + tid];
        sg[tid] = g;
        sarea[tid] = (g.z - g.x) * (g.w - g.y);
    }
    __syncthreads();

    const int n = blockIdx.x * 256 + tid;
    float4 p = prop_boxes[b * NPROP + n];
    const float areaP = (p.z - p.x) * (p.w - p.y);

    // Init so m=0 always wins the first compare (matches argmax first-index).
    float bi = -1.0f;   // best inter
    float bu = 1.0f;    // best union (positive)
    int   bm = 0;

#pragma unroll 8
    for (int m = 0; m < MGT; m++) {
        float4 g = sg[m];
        float x1 = fmaxf(g.x, p.x);
        float y1 = fmaxf(g.y, p.y);
        float x2 = fminf(g.z, p.z);
        float y2 = fminf(g.w, p.w);
        float w  = fmaxf(x2 - x1, 0.0f);
        float h  = fmaxf(y2 - y1, 0.0f);
        float inter = w * h;
        float uni   = sarea[m] + areaP - inter;
        // inter/uni > bi/bu  <=>  inter*bu > bi*uni   (uni, bu > 0)
        if (inter * bu > bi * uni) { bi = inter; bu = uni; bm = m; }
    }

    const float val = bi / bu;   // single IEEE division per proposal

    out[b * NPROP + n] = val;                                  // matched_vals
    out[BATCH * NPROP + b * NPROP + n] = (float)bm;            // matched_idxs

    // Sort key: ascending sort == (priority descending, index ascending).
    float pri = rand_priority[b * NPROP + n];
    unsigned int pu = __float_as_uint(pri);
    pu = (pu & 0x80000000u) ? ~pu : (pu | 0x80000000u);        // order-preserving
    unsigned int inv = ~pu;                                    // descending pri
    bool fg = (val >= 0.5f);

    unsigned long long masked_out = (0xFFFFFFFFULL << 32) | (unsigned long long)n;
    unsigned long long live       = ((unsigned long long)inv << 32) | (unsigned long long)n;

    g_keys[(0ULL * BATCH + b) * NPROP + n] = fg ? live : masked_out;
    g_keys[(1ULL * BATCH + b) * NPROP + n] = fg ? masked_out : live;
}

// ---------------------------------------------------------------------------
// Kernel B: per (batch, fg/bg) full bitonic sort of 8192 keys in 64KB smem,
// then emit sampled_idxs / sampled_classes / sampled_gt.
// ---------------------------------------------------------------------------
extern __shared__ unsigned long long sk[];

__global__ __launch_bounds__(SORT_THREADS)
void sample_sort_kernel(const int* __restrict__ gt_classes,
                        float* __restrict__ out)
{
    const int b = blockIdx.x;   // 0..15
    const int s = blockIdx.y;   // 0 = fg, 1 = bg
    const int tid = threadIdx.x;

    const unsigned long long* keys = g_keys + ((size_t)s * BATCH + b) * NPROP;

#pragma unroll
    for (int i = tid; i < NPROP; i += SORT_THREADS) sk[i] = keys[i];
    __syncthreads();

    // Ascending bitonic sort of 8192 elements.
    for (int k = 2; k <= NPROP; k <<= 1) {
        for (int j = k >> 1; j > 0; j >>= 1) {
#pragma unroll
            for (int i = tid; i < NPROP; i += SORT_THREADS) {
                int ixj = i ^ j;
                if (ixj > i) {
                    unsigned long long a = sk[i];
                    unsigned long long c = sk[ixj];
                    bool up = ((i & k) == 0);
                    if ((a > c) == up) { sk[i] = c; sk[ixj] = a; }
                }
            }
            __syncthreads();
        }
    }

    const int kcnt = (s == 0) ? KFG : KBG;
    const int off  = (s == 0) ? 0   : KFG;

    if (tid < kcnt) {
        unsigned long long key = sk[tid];
        int n = (int)(key & (unsigned long long)(NPROP - 1));
        bool valid = ((unsigned int)(key >> 32)) != 0xFFFFFFFFu;

        float val = out[b * NPROP + n];
        int midx  = (int)out[BATCH * NPROP + b * NPROP + n];
        int cls   = (val >= 0.5f) ? gt_classes[b * MGT + midx] : NUM_CLASSES;

        const int base = 2 * BATCH * NPROP;
        const int slot = b * NSAMP + off + tid;
        out[base + slot]                    = (float)n;                        // sampled_idxs
        out[base + BATCH * NSAMP + slot]    = valid ? (float)cls  : -1.0f;     // sampled_classes
        out[base + 2 * BATCH * NSAMP + slot]= valid ? (float)midx : -1.0f;     // sampled_gt
    }
}

// ---------------------------------------------------------------------------
extern "C" void kernel_launch(void* const* d_in, const int* in_sizes, int n_in,
                              void* d_out, int out_size)
{
    const float4* gt_boxes   = (const float4*)d_in[0];
    const int*    gt_classes = (const int*)  d_in[1];
    const float4* prop_boxes = (const float4*)d_in[2];
    const float*  rand_pri   = (const float*)d_in[3];
    float* out = (float*)d_out;

    (void)in_sizes; (void)n_in; (void)out_size;

    cudaFuncSetAttribute(sample_sort_kernel,
                         cudaFuncAttributeMaxDynamicSharedMemorySize,
                         NPROP * sizeof(unsigned long long));

    dim3 gridA(NPROP / 256, BATCH);
    iou_match_kernel<<<gridA, 256>>>(gt_boxes, prop_boxes, rand_pri, out);

    dim3 gridB(BATCH, 2);
    sample_sort_kernel<<<gridB, SORT_THREADS, NPROP * sizeof(unsigned long long)>>>(
        gt_classes, out);
}

// round 3
// speedup vs baseline: 2.6309x; 2.6309x over previous
#include <cuda_runtime.h>
#include <cuda_bf16.h>

#define BATCH 16
#define MGT 256
#define NPROP 8192
#define NUM_CLASSES 80
#define KFG 128
#define KBG 384
#define NSAMP 512

#define RADIX_BINS 4096

// Scratch: 45-bit sort keys ((inv_pri<<13)|n) for [fg|bg] x batch x proposals
__device__ unsigned long long g_keys[2ULL * BATCH * NPROP];

// ---------------------------------------------------------------------------
// Kernel A: per-proposal max-IoU match (division-free argmax), 2 proposals
// per thread to amortize the shared-memory GT loads.
// ---------------------------------------------------------------------------
__global__ __launch_bounds__(256)
void iou_match_kernel(const float4* __restrict__ gt_boxes,
                      const float4* __restrict__ prop_boxes,
                      const float* __restrict__ rand_priority,
                      float* __restrict__ out)
{
    __shared__ float4 sg[MGT];
    __shared__ float sarea[MGT];

    const int b   = blockIdx.y;
    const int tid = threadIdx.x;

    {
        float4 g = gt_boxes[b * MGT + tid];
        sg[tid] = g;
        sarea[tid] = (g.z - g.x) * (g.w - g.y);
    }
    __syncthreads();

    const int n0 = blockIdx.x * 512 + tid;
    const int n1 = n0 + 256;

    float4 p0 = prop_boxes[b * NPROP + n0];
    float4 p1 = prop_boxes[b * NPROP + n1];
    const float a0 = (p0.z - p0.x) * (p0.w - p0.y);
    const float a1 = (p1.z - p1.x) * (p1.w - p1.y);

    float bi0 = -1.0f, bu0 = 1.0f; int bm0 = 0;
    float bi1 = -1.0f, bu1 = 1.0f; int bm1 = 0;

#pragma unroll 4
    for (int m = 0; m < MGT; m++) {
        float4 g = sg[m];
        float ga = sarea[m];
        {
            float w = fmaxf(fminf(g.z, p0.z) - fmaxf(g.x, p0.x), 0.0f);
            float h = fmaxf(fminf(g.w, p0.w) - fmaxf(g.y, p0.y), 0.0f);
            float inter = w * h;
            float uni   = ga + a0 - inter;
            if (inter * bu0 > bi0 * uni) { bi0 = inter; bu0 = uni; bm0 = m; }
        }
        {
            float w = fmaxf(fminf(g.z, p1.z) - fmaxf(g.x, p1.x), 0.0f);
            float h = fmaxf(fminf(g.w, p1.w) - fmaxf(g.y, p1.y), 0.0f);
            float inter = w * h;
            float uni   = ga + a1 - inter;
            if (inter * bu1 > bi1 * uni) { bi1 = inter; bu1 = uni; bm1 = m; }
        }
    }

    const float* pri_row = rand_priority + b * NPROP;
    unsigned long long* fg_keys = g_keys + (size_t)b * NPROP;
    unsigned long long* bg_keys = g_keys + (size_t)(BATCH + b) * NPROP;

#pragma unroll
    for (int q = 0; q < 2; q++) {
        int   n   = q ? n1 : n0;
        float bi  = q ? bi1 : bi0;
        float bu  = q ? bu1 : bu0;
        int   bm  = q ? bm1 : bm0;

        float val = bi / bu;
        out[b * NPROP + n] = val;                       // matched_vals
        out[BATCH * NPROP + b * NPROP + n] = (float)bm; // matched_idxs

        unsigned int pu = __float_as_uint(pri_row[n]);
        pu = (pu & 0x80000000u) ? ~pu : (pu | 0x80000000u); // order-preserving map
        unsigned int inv = ~pu;                              // descending priority
        bool fg = (val >= 0.5f);

        unsigned long long live   = ((unsigned long long)inv << 13) | (unsigned long long)n;
        unsigned long long masked = (0xFFFFFFFFULL << 13)          | (unsigned long long)n;

        fg_keys[n] = fg ? live : masked;
        bg_keys[n] = fg ? masked : live;
    }
}

// ---------------------------------------------------------------------------
// Kernel B: per (batch, fg/bg) exact top-k via MSB radix select on unique
// 45-bit keys, then bitonic sort of only the k winners, then emit.
// ---------------------------------------------------------------------------
__global__ __launch_bounds__(1024)
void select_kernel(const int* __restrict__ gt_classes,
                   float* __restrict__ out)
{
    __shared__ unsigned int hist[RADIX_BINS];
    __shared__ unsigned int warp_pref[32];      // exclusive prefix per warp
    __shared__ unsigned long long cand[NSAMP];
    __shared__ int sel_bin;
    __shared__ unsigned int sel_excl;
    __shared__ unsigned int s_cnt;

    const int b = blockIdx.x;      // batch
    const int s = blockIdx.y;      // 0=fg, 1=bg
    const int tid  = threadIdx.x;
    const int lane = tid & 31;
    const int wid  = tid >> 5;

    const unsigned long long* keys = g_keys + ((size_t)s * BATCH + b) * NPROP;

    unsigned long long k64[8];
#pragma unroll
    for (int j = 0; j < 8; j++) k64[j] = keys[tid + j * 1024];

    const unsigned int ksel = (s == 0) ? KFG : KBG;   // rank wanted (1-indexed)
    unsigned int kk = ksel;
    unsigned long long prefix = 0, mask = 0;

#pragma unroll
    for (int r = 0; r < 4; r++) {
        const int shift = (r < 3) ? (33 - 12 * r) : 0;
        const unsigned long long digmask = (r < 3) ? 4095ULL : 511ULL;

        // zero histogram
#pragma unroll
        for (int i = tid; i < RADIX_BINS; i += 1024) hist[i] = 0;
        __syncthreads();

        // count digits of surviving candidates
#pragma unroll
        for (int j = 0; j < 8; j++) {
            if ((k64[j] & mask) == prefix)
                atomicAdd(&hist[(unsigned int)((k64[j] >> shift) & digmask)], 1u);
        }
        __syncthreads();

        // block-wide exclusive scan over 4096 bins (4 per thread)
        unsigned int h0 = hist[4 * tid + 0];
        unsigned int h1 = hist[4 * tid + 1];
        unsigned int h2 = hist[4 * tid + 2];
        unsigned int h3 = hist[4 * tid + 3];
        unsigned int lsum = h0 + h1 + h2 + h3;

        unsigned int x = lsum;
#pragma unroll
        for (int o = 1; o < 32; o <<= 1) {
            unsigned int y = __shfl_up_sync(0xFFFFFFFFu, x, o);
            if (lane >= o) x += y;
        }
        if (lane == 31) warp_pref[wid] = x;   // warp total (inclusive of last)
        __syncthreads();
        if (wid == 0) {
            unsigned int v = warp_pref[lane];
            unsigned int xx = v;
#pragma unroll
            for (int o = 1; o < 32; o <<= 1) {
                unsigned int y = __shfl_up_sync(0xFFFFFFFFu, xx, o);
                if (lane >= o) xx += y;
            }
            warp_pref[lane] = xx - v;         // exclusive prefix of warp totals
        }
        __syncthreads();

        unsigned int e = warp_pref[wid] + (x - lsum);   // excl prefix of bin 4*tid
        // locate the bin containing rank kk
        unsigned int e0 = e, e1 = e + h0, e2 = e1 + h1, e3 = e2 + h2;
        if (kk > e0 && kk <= e0 + h0) { sel_bin = 4 * tid + 0; sel_excl = e0; }
        if (kk > e1 && kk <= e1 + h1) { sel_bin = 4 * tid + 1; sel_excl = e1; }
        if (kk > e2 && kk <= e2 + h2) { sel_bin = 4 * tid + 2; sel_excl = e2; }
        if (kk > e3 && kk <= e3 + h3) { sel_bin = 4 * tid + 3; sel_excl = e3; }
        __syncthreads();

        prefix |= ((unsigned long long)sel_bin) << shift;
        mask   |= digmask << shift;
        kk     -= sel_excl;
        __syncthreads();
    }

    // prefix == k-th smallest key; keys unique -> exactly ksel keys <= prefix
    if (tid == 0) s_cnt = 0;
    __syncthreads();
#pragma unroll
    for (int j = 0; j < 8; j++) {
        if (k64[j] <= prefix) {
            unsigned int pos = atomicAdd(&s_cnt, 1u);
            cand[pos] = k64[j];
        }
    }
    __syncthreads();

    // pad to 512 with +inf sentinels, then ascending bitonic sort of 512
    if (tid >= (int)ksel && tid < NSAMP) cand[tid] = 0xFFFFFFFFFFFFFFFFULL;
    __syncthreads();

    for (int kstep = 2; kstep <= NSAMP; kstep <<= 1) {
        for (int j = kstep >> 1; j > 0; j >>= 1) {
            if (tid < NSAMP) {
                int ixj = tid ^ j;
                if (ixj > tid) {
                    unsigned long long a = cand[tid];
                    unsigned long long c = cand[ixj];
                    bool up = ((tid & kstep) == 0);
                    if ((a > c) == up) { cand[tid] = c; cand[ixj] = a; }
                }
            }
            __syncthreads();
        }
    }

    const int kcnt = (s == 0) ? KFG : KBG;
    const int off  = (s == 0) ? 0   : KFG;

    if (tid < kcnt) {
        unsigned long long key = cand[tid];
        int n = (int)(key & (unsigned long long)(NPROP - 1));
        bool valid = ((unsigned int)(key >> 13)) != 0xFFFFFFFFu;

        float val = out[b * NPROP + n];
        int midx  = (int)out[BATCH * NPROP + b * NPROP + n];
        int cls   = (val >= 0.5f) ? gt_classes[b * MGT + midx] : NUM_CLASSES;

        const int base = 2 * BATCH * NPROP;
        const int slot = b * NSAMP + off + tid;
        out[base + slot]                     = (float)n;                     // sampled_idxs
        out[base + BATCH * NSAMP + slot]     = valid ? (float)cls  : -1.0f;  // sampled_classes
        out[base + 2 * BATCH * NSAMP + slot] = valid ? (float)midx : -1.0f;  // sampled_gt
    }
}

// ---------------------------------------------------------------------------
extern "C" void kernel_launch(void* const* d_in, const int* in_sizes, int n_in,
                              void* d_out, int out_size)
{
    const float4* gt_boxes   = (const float4*)d_in[0];
    const int*    gt_classes = (const int*)  d_in[1];
    const float4* prop_boxes = (const float4*)d_in[2];
    const float*  rand_pri   = (const float*)d_in[3];
    float* out = (float*)d_out;

    (void)in_sizes; (void)n_in; (void)out_size;

    dim3 gridA(NPROP / 512, BATCH);
    iou_match_kernel<<<gridA, 256>>>(gt_boxes, prop_boxes, rand_pri, out);

    dim3 gridB(BATCH, 2);
    select_kernel<<<gridB, 1024>>>(gt_classes, out);
}